// round 2
// baseline (speedup 1.0000x reference)
#include <cuda_runtime.h>

// Problem-size constants (fixed by the dataset: setup_inputs()).
#define NNODES 50000
#define NEDGES 400000
#define FEAT   64
#define HEADS  4

// ---------------- scratch (static device globals; no allocation) ----------------
__device__ float g_Qp[(size_t)NNODES * 256];   // Q' = x @ M_h, layout [n][h*64+d]  (51.2 MB)
__device__ float g_T [(size_t)NNODES * 256];   // T  = segment softmax-weighted sum of x_s, same layout
__device__ float g_M [HEADS * 64 * 64];        // M_h = Wq_h @ Wk_h^T * scale
__device__ float g_Wst[256 * 64];              // Wst[h*64+f][c] = (Wv_h @ Wout)[f][c] / HEADS
__device__ int   g_deg   [NNODES];
__device__ int   g_rowptr[NNODES + 1];
__device__ int   g_cursor[NNODES];
__device__ int   g_esend [NEDGES];

// ---------------- small matrix prep ----------------
// blocks 0..3: M_h = Wq_h @ Wk_h^T * 0.125
// blocks 4..7: Wst_h = Wv_h @ Wout * 0.25
__global__ __launch_bounds__(256) void prep_mats_kernel(
    const float* __restrict__ Wq, const float* __restrict__ Wk,
    const float* __restrict__ Wv, const float* __restrict__ Wout)
{
    __shared__ float As[64 * 65];
    __shared__ float Bs[64 * 65];
    int b = blockIdx.x;
    int tid = threadIdx.x;

    if (b < 4) {
        int h = b;
        const float* A = Wq + h * 4096;
        const float* B = Wk + h * 4096;
        for (int i = tid; i < 4096; i += 256) {
            As[(i >> 6) * 65 + (i & 63)] = A[i];
            Bs[(i >> 6) * 65 + (i & 63)] = B[i];
        }
        __syncthreads();
        // M[f1][f2] = sum_d Wq[f1][d]*Wk[f2][d] * 0.125
        for (int o = tid; o < 4096; o += 256) {
            int f1 = o & 63, f2 = o >> 6;
            float s = 0.f;
            #pragma unroll 8
            for (int d = 0; d < 64; d++)
                s += As[f1 * 65 + d] * Bs[f2 * 65 + d];
            g_M[h * 4096 + f1 * 64 + f2] = s * 0.125f;
        }
    } else {
        int h = b - 4;
        const float* A = Wv + h * 4096;   // [f][d]
        for (int i = tid; i < 4096; i += 256) {
            As[(i >> 6) * 65 + (i & 63)] = A[i];
            Bs[(i >> 6) * 65 + (i & 63)] = Wout[i];  // [d][c]
        }
        __syncthreads();
        // Wst[h*64+f][c] = sum_d Wv[f][d]*Wout[d][c] * 0.25
        for (int o = tid; o < 4096; o += 256) {
            int f = o & 63, c = o >> 6;
            float s = 0.f;
            #pragma unroll 8
            for (int d = 0; d < 64; d++)
                s += As[f * 65 + d] * Bs[d * 65 + c];
            g_Wst[(h * 64 + f) * 64 + c] = s * 0.25f;
        }
    }
}

// ---------------- CSR build ----------------
__global__ void zero_deg_kernel(int n) {
    int i = blockIdx.x * blockDim.x + threadIdx.x;
    if (i < n) g_deg[i] = 0;
}

__global__ void count_deg_kernel(const int* __restrict__ recv, int E) {
    int i = blockIdx.x * blockDim.x + threadIdx.x;
    if (i < E) atomicAdd(&g_deg[recv[i]], 1);
}

// Single-block chunked exclusive scan of g_deg -> g_rowptr, g_cursor
__global__ __launch_bounds__(1024, 1) void scan_kernel(int n) {
    __shared__ int wsum[32];
    __shared__ int carry;
    int tid = threadIdx.x, lane = tid & 31, wid = tid >> 5;
    if (tid == 0) carry = 0;
    __syncthreads();
    for (int base = 0; base < n; base += 1024) {
        int i = base + tid;
        int v = (i < n) ? g_deg[i] : 0;
        int xi = v;
        #pragma unroll
        for (int o = 1; o < 32; o <<= 1) {
            int t = __shfl_up_sync(0xffffffffu, xi, o);
            if (lane >= o) xi += t;
        }
        if (lane == 31) wsum[wid] = xi;
        __syncthreads();
        if (wid == 0) {
            int s = wsum[lane];
            #pragma unroll
            for (int o = 1; o < 32; o <<= 1) {
                int t = __shfl_up_sync(0xffffffffu, s, o);
                if (lane >= o) s += t;
            }
            wsum[lane] = s;
        }
        __syncthreads();
        int incl = xi + (wid ? wsum[wid - 1] : 0) + carry;
        if (i < n) {
            g_rowptr[i] = incl - v;
            g_cursor[i] = incl - v;
        }
        __syncthreads();
        if (tid == 1023) carry = incl;
        __syncthreads();
    }
    if (tid == 0) g_rowptr[n] = carry;
}

__global__ void scatter_edges_kernel(const int* __restrict__ send,
                                     const int* __restrict__ recv, int E) {
    int i = blockIdx.x * blockDim.x + threadIdx.x;
    if (i < E) {
        int pos = atomicAdd(&g_cursor[recv[i]], 1);
        g_esend[pos] = send[i];
    }
}

// ---------------- GEMM 1: Q' = x @ M_h  (per head) ----------------
// block tile 128 rows x 64 cols, 256 threads, 8x4 micro-tile
__global__ __launch_bounds__(256) void gemm_qp_kernel(const float* __restrict__ x, int n) {
    __shared__ float As[128][64];  // x tile [row][k]   32 KB
    __shared__ float Bs[64][64];   // M_h   [k][c]      16 KB
    int h = blockIdx.y;
    int row0 = blockIdx.x * 128;
    int tid = threadIdx.x;

    const float4* Bg = reinterpret_cast<const float4*>(g_M + h * 4096);
    for (int i = tid; i < 1024; i += 256)
        reinterpret_cast<float4*>(&Bs[0][0])[i] = Bg[i];

    for (int i = tid; i < 2048; i += 256) {
        int r = i >> 4, k4 = (i & 15) << 2;
        int gr = row0 + r;
        float4 v = make_float4(0.f, 0.f, 0.f, 0.f);
        if (gr < n) v = *reinterpret_cast<const float4*>(x + (size_t)gr * 64 + k4);
        *reinterpret_cast<float4*>(&As[r][k4]) = v;
    }
    __syncthreads();

    int rg = tid >> 4;   // 0..15 -> rows rg*8..+7
    int cg = tid & 15;   // 0..15 -> cols cg*4..+3
    float4 acc[8];
    #pragma unroll
    for (int i = 0; i < 8; i++) acc[i] = make_float4(0.f, 0.f, 0.f, 0.f);

    #pragma unroll 8
    for (int k = 0; k < 64; k++) {
        float4 bv = *reinterpret_cast<const float4*>(&Bs[k][cg << 2]);
        #pragma unroll
        for (int i = 0; i < 8; i++) {
            float a = As[(rg << 3) + i][k];
            acc[i].x += a * bv.x; acc[i].y += a * bv.y;
            acc[i].z += a * bv.z; acc[i].w += a * bv.w;
        }
    }

    #pragma unroll
    for (int i = 0; i < 8; i++) {
        int gr = row0 + (rg << 3) + i;
        if (gr < n)
            *reinterpret_cast<float4*>(g_Qp + (size_t)gr * 256 + h * 64 + (cg << 2)) = acc[i];
    }
}

// ---------------- fused attention: online segment softmax + weighted sum ----------------
// one warp per receiver; lane l handles head h=l/8, feature chunk d=(l%8)*8..+7
__global__ __launch_bounds__(256) void attn_kernel(const float* __restrict__ x, int n) {
    int r = (blockIdx.x << 3) + (threadIdx.x >> 5);
    if (r >= n) return;
    int lane = threadIdx.x & 31;
    int j = lane & 7;

    const float4* qr = reinterpret_cast<const float4*>(g_Qp + (size_t)r * 256);
    float4 q0 = qr[lane * 2], q1 = qr[lane * 2 + 1];

    int beg = g_rowptr[r], end = g_rowptr[r + 1];
    float m = -1e30f, dsum = 0.f;
    float4 a0 = make_float4(0.f, 0.f, 0.f, 0.f);
    float4 a1 = a0;

    for (int p = beg; p < end; p++) {
        int s = g_esend[p];
        const float4* xs = reinterpret_cast<const float4*>(x + (size_t)s * 64);
        float4 v0 = xs[j * 2], v1 = xs[j * 2 + 1];

        float part = q0.x * v0.x + q0.y * v0.y + q0.z * v0.z + q0.w * v0.w
                   + q1.x * v1.x + q1.y * v1.y + q1.z * v1.z + q1.w * v1.w;
        part += __shfl_xor_sync(0xffffffffu, part, 1);
        part += __shfl_xor_sync(0xffffffffu, part, 2);
        part += __shfl_xor_sync(0xffffffffu, part, 4);
        // part == score s_eh (scale folded into M)

        float mn = fmaxf(m, part);
        float c  = __expf(m - mn);
        float pe = __expf(part - mn);
        dsum = dsum * c + pe;
        a0.x = a0.x * c + pe * v0.x; a0.y = a0.y * c + pe * v0.y;
        a0.z = a0.z * c + pe * v0.z; a0.w = a0.w * c + pe * v0.w;
        a1.x = a1.x * c + pe * v1.x; a1.y = a1.y * c + pe * v1.y;
        a1.z = a1.z * c + pe * v1.z; a1.w = a1.w * c + pe * v1.w;
        m = mn;
    }

    float rinv = (dsum > 0.f) ? (1.0f / dsum) : 0.f;
    a0.x *= rinv; a0.y *= rinv; a0.z *= rinv; a0.w *= rinv;
    a1.x *= rinv; a1.y *= rinv; a1.z *= rinv; a1.w *= rinv;

    float4* tr = reinterpret_cast<float4*>(g_T + (size_t)r * 256);
    tr[lane * 2] = a0;
    tr[lane * 2 + 1] = a1;
}

// ---------------- GEMM 2: out = x + T @ Wst   (N x 256) @ (256 x 64) ----------------
__global__ __launch_bounds__(256) void gemm_out_kernel(const float* __restrict__ x,
                                                       float* __restrict__ out, int n) {
    __shared__ float As[128][64];  // T chunk [row][k]
    __shared__ float Bs[64][64];   // Wst chunk [k][c]
    int row0 = blockIdx.x * 128;
    int tid = threadIdx.x;
    int rg = tid >> 4, cg = tid & 15;

    float4 acc[8];
    #pragma unroll
    for (int i = 0; i < 8; i++) acc[i] = make_float4(0.f, 0.f, 0.f, 0.f);

    for (int kc = 0; kc < 4; kc++) {
        const float4* Bg = reinterpret_cast<const float4*>(g_Wst + kc * 64 * 64);
        for (int i = tid; i < 1024; i += 256)
            reinterpret_cast<float4*>(&Bs[0][0])[i] = Bg[i];
        for (int i = tid; i < 2048; i += 256) {
            int r = i >> 4, k4 = (i & 15) << 2;
            int gr = row0 + r;
            float4 v = make_float4(0.f, 0.f, 0.f, 0.f);
            if (gr < n) v = *reinterpret_cast<const float4*>(g_T + (size_t)gr * 256 + kc * 64 + k4);
            *reinterpret_cast<float4*>(&As[r][k4]) = v;
        }
        __syncthreads();

        #pragma unroll 8
        for (int k = 0; k < 64; k++) {
            float4 bv = *reinterpret_cast<const float4*>(&Bs[k][cg << 2]);
            #pragma unroll
            for (int i = 0; i < 8; i++) {
                float a = As[(rg << 3) + i][k];
                acc[i].x += a * bv.x; acc[i].y += a * bv.y;
                acc[i].z += a * bv.z; acc[i].w += a * bv.w;
            }
        }
        __syncthreads();
    }

    #pragma unroll
    for (int i = 0; i < 8; i++) {
        int gr = row0 + (rg << 3) + i;
        if (gr < n) {
            float4 xv = *reinterpret_cast<const float4*>(x + (size_t)gr * 64 + (cg << 2));
            acc[i].x += xv.x; acc[i].y += xv.y; acc[i].z += xv.z; acc[i].w += xv.w;
            *reinterpret_cast<float4*>(out + (size_t)gr * 64 + (cg << 2)) = acc[i];
        }
    }
}

// ---------------- launch ----------------
extern "C" void kernel_launch(void* const* d_in, const int* in_sizes, int n_in,
                              void* d_out, int out_size) {
    const float* x    = (const float*)d_in[0];
    const float* Wq   = (const float*)d_in[1];
    const float* Wk   = (const float*)d_in[2];
    const float* Wv   = (const float*)d_in[3];
    const float* Wout = (const float*)d_in[4];
    const int*   ei   = (const int*)d_in[5];

    int n = in_sizes[0] / FEAT;       // 50000
    int E = in_sizes[5] / 2;          // 400000
    const int* send = ei;
    const int* recv = ei + E;

    // small weight products
    prep_mats_kernel<<<8, 256>>>(Wq, Wk, Wv, Wout);

    // CSR build
    zero_deg_kernel<<<(n + 255) / 256, 256>>>(n);
    count_deg_kernel<<<(E + 255) / 256, 256>>>(recv, E);
    scan_kernel<<<1, 1024>>>(n);
    scatter_edges_kernel<<<(E + 255) / 256, 256>>>(send, recv, E);

    // Q' projection
    dim3 g1((n + 127) / 128, HEADS);
    gemm_qp_kernel<<<g1, 256>>>(x, n);

    // fused per-receiver attention (online softmax)
    attn_kernel<<<(n + 7) / 8, 256>>>(x, n);

    // output projection + residual
    gemm_out_kernel<<<(n + 127) / 128, 256>>>(x, (float*)d_out, n);
}

// round 3
// speedup vs baseline: 1.9719x; 1.9719x over previous
#include <cuda_runtime.h>

#define NNODES 50000
#define NEDGES 400000
#define FEAT   64
#define HEADS  4

// ---------------- scratch (static device globals; no allocation) ----------------
__device__ float g_Qp[(size_t)NNODES * 256];   // Q' = x @ M_h, layout [n][h*64+d]
__device__ float g_T [(size_t)NNODES * 256];   // segment-softmax-weighted sums of x_s
__device__ float g_M [HEADS * 64 * 64];        // M_h = Wq_h @ Wk_h^T * scale
__device__ float g_Wst[256 * 64];              // Wst[h*64+f][c] = (Wv_h @ Wout)[f][c] / HEADS
__device__ int   g_deg   [NNODES];
__device__ int   g_rowptr[NNODES + 1];
__device__ int   g_cursor[NNODES];
__device__ int   g_esend [NEDGES];
__device__ int   g_bsum  [64];
__device__ int   g_bsumx [64];

// packed f32x2 helpers
#define FMA2(acc, a, b) asm("fma.rn.f32x2 %0, %1, %2, %0;" : "+l"(acc) : "l"(a), "l"(b))
#define ADD2(d, a, b)   asm("add.rn.f32x2 %0, %1, %2;" : "=l"(d) : "l"(a), "l"(b))
#define DUP2(d, a)      asm("mov.b64 %0, {%1, %1};" : "=l"(d) : "r"(a))

// ---------------- small matrix prep ----------------
__global__ __launch_bounds__(256) void prep_mats_kernel(
    const float* __restrict__ Wq, const float* __restrict__ Wk,
    const float* __restrict__ Wv, const float* __restrict__ Wout)
{
    __shared__ float As[64 * 65];
    __shared__ float Bs[64 * 65];
    int b = blockIdx.x;
    int tid = threadIdx.x;

    if (b < 4) {
        int h = b;
        const float* A = Wq + h * 4096;
        const float* B = Wk + h * 4096;
        for (int i = tid; i < 4096; i += 256) {
            As[(i >> 6) * 65 + (i & 63)] = A[i];
            Bs[(i >> 6) * 65 + (i & 63)] = B[i];
        }
        __syncthreads();
        for (int o = tid; o < 4096; o += 256) {
            int f1 = o & 63, f2 = o >> 6;
            float s = 0.f;
            #pragma unroll 8
            for (int d = 0; d < 64; d++)
                s += As[f1 * 65 + d] * Bs[f2 * 65 + d];
            g_M[h * 4096 + f1 * 64 + f2] = s * 0.125f;
        }
    } else {
        int h = b - 4;
        const float* A = Wv + h * 4096;
        for (int i = tid; i < 4096; i += 256) {
            As[(i >> 6) * 65 + (i & 63)] = A[i];
            Bs[(i >> 6) * 65 + (i & 63)] = Wout[i];
        }
        __syncthreads();
        for (int o = tid; o < 4096; o += 256) {
            int f = o & 63, c = o >> 6;
            float s = 0.f;
            #pragma unroll 8
            for (int d = 0; d < 64; d++)
                s += As[f * 65 + d] * Bs[d * 65 + c];
            g_Wst[(h * 64 + f) * 64 + c] = s * 0.25f;
        }
    }
}

// ---------------- CSR build ----------------
__global__ void zero_deg_kernel(int n) {
    int i = blockIdx.x * blockDim.x + threadIdx.x;
    if (i < n) g_deg[i] = 0;
}

__global__ void count_deg_kernel(const int* __restrict__ recv, int E) {
    int i = blockIdx.x * blockDim.x + threadIdx.x;
    if (i < E) atomicAdd(&g_deg[recv[i]], 1);
}

// pass 1: per-block (1024-wide) local exclusive scan; block sums to g_bsum
__global__ __launch_bounds__(1024) void scan_blocks_kernel(int n) {
    __shared__ int wsum[32];
    int b = blockIdx.x;
    int tid = threadIdx.x, lane = tid & 31, wid = tid >> 5;
    int i = (b << 10) + tid;
    int v = (i < n) ? g_deg[i] : 0;
    int xi = v;
    #pragma unroll
    for (int o = 1; o < 32; o <<= 1) {
        int t = __shfl_up_sync(0xffffffffu, xi, o);
        if (lane >= o) xi += t;
    }
    if (lane == 31) wsum[wid] = xi;
    __syncthreads();
    if (wid == 0) {
        int s = wsum[lane];
        #pragma unroll
        for (int o = 1; o < 32; o <<= 1) {
            int t = __shfl_up_sync(0xffffffffu, s, o);
            if (lane >= o) s += t;
        }
        wsum[lane] = s;
    }
    __syncthreads();
    int incl = xi + (wid ? wsum[wid - 1] : 0);
    if (i < n) g_rowptr[i] = incl - v;      // local exclusive
    if (tid == 1023) g_bsum[b] = incl;
}

// pass 2: one warp scans <=64 block sums (2 per lane), writes g_bsumx + total
__global__ __launch_bounds__(32) void scan_tops_kernel(int nb, int n) {
    int lane = threadIdx.x;
    int v0 = (lane < nb) ? g_bsum[lane] : 0;
    int v1 = (lane + 32 < nb) ? g_bsum[lane + 32] : 0;
    int s0 = v0;
    #pragma unroll
    for (int o = 1; o < 32; o <<= 1) {
        int t = __shfl_up_sync(0xffffffffu, s0, o);
        if (lane >= o) s0 += t;
    }
    int tot0 = __shfl_sync(0xffffffffu, s0, 31);
    int s1 = v1;
    #pragma unroll
    for (int o = 1; o < 32; o <<= 1) {
        int t = __shfl_up_sync(0xffffffffu, s1, o);
        if (lane >= o) s1 += t;
    }
    s1 += tot0;
    g_bsumx[lane] = s0 - v0;
    g_bsumx[lane + 32] = s1 - v1;
    if (lane == 31) g_rowptr[n] = s1;   // total edge count
}

// pass 3: add block offsets, seed cursors
__global__ __launch_bounds__(1024) void scan_add_kernel(int n) {
    int i = (blockIdx.x << 10) + threadIdx.x;
    if (i < n) {
        int r = g_rowptr[i] + g_bsumx[blockIdx.x];
        g_rowptr[i] = r;
        g_cursor[i] = r;
    }
}

__global__ void scatter_edges_kernel(const int* __restrict__ send,
                                     const int* __restrict__ recv, int E) {
    int i = blockIdx.x * blockDim.x + threadIdx.x;
    if (i < E) {
        int pos = atomicAdd(&g_cursor[recv[i]], 1);
        g_esend[pos] = send[i];
    }
}

// ---------------- GEMM 1: Q' = x @ M_h  (per head), f32x2-packed ----------------
// block: 128 rows x 64 cols, 256 threads; micro-tile 8 rows x 4 cols (2 packed)
__global__ __launch_bounds__(256) void gemm_qp_kernel(const float* __restrict__ x, int n) {
    __shared__ float As[128][64];
    __shared__ float Bs[64][64];
    int h = blockIdx.y;
    int row0 = blockIdx.x * 128;
    int tid = threadIdx.x;

    const float4* Bg = reinterpret_cast<const float4*>(g_M + h * 4096);
    for (int i = tid; i < 1024; i += 256)
        reinterpret_cast<float4*>(&Bs[0][0])[i] = Bg[i];
    for (int i = tid; i < 2048; i += 256) {
        int r = i >> 4, k4 = (i & 15) << 2;
        int gr = row0 + r;
        float4 v = make_float4(0.f, 0.f, 0.f, 0.f);
        if (gr < n) v = *reinterpret_cast<const float4*>(x + (size_t)gr * 64 + k4);
        *reinterpret_cast<float4*>(&As[r][k4]) = v;
    }
    __syncthreads();

    int rg = tid >> 4;   // 0..15 -> rows rg*8..+7
    int cg = tid & 15;   // 0..15 -> cols cg*4..+3
    unsigned long long acc[8][2];
    #pragma unroll
    for (int i = 0; i < 8; i++) { acc[i][0] = 0ull; acc[i][1] = 0ull; }

    #pragma unroll 8
    for (int k = 0; k < 64; k += 2) {
        unsigned long long b00 = *reinterpret_cast<const unsigned long long*>(&Bs[k][cg << 2]);
        unsigned long long b01 = *reinterpret_cast<const unsigned long long*>(&Bs[k][(cg << 2) + 2]);
        unsigned long long b10 = *reinterpret_cast<const unsigned long long*>(&Bs[k + 1][cg << 2]);
        unsigned long long b11 = *reinterpret_cast<const unsigned long long*>(&Bs[k + 1][(cg << 2) + 2]);
        #pragma unroll
        for (int i = 0; i < 8; i++) {
            unsigned long long a2 = *reinterpret_cast<const unsigned long long*>(&As[(rg << 3) + i][k]);
            unsigned int alo, ahi;
            asm("mov.b64 {%0, %1}, %2;" : "=r"(alo), "=r"(ahi) : "l"(a2));
            unsigned long long aa0, aa1;
            DUP2(aa0, alo);
            DUP2(aa1, ahi);
            FMA2(acc[i][0], aa0, b00);
            FMA2(acc[i][1], aa0, b01);
            FMA2(acc[i][0], aa1, b10);
            FMA2(acc[i][1], aa1, b11);
        }
    }

    #pragma unroll
    for (int i = 0; i < 8; i++) {
        int gr = row0 + (rg << 3) + i;
        if (gr < n) {
            ulonglong2 o;
            o.x = acc[i][0]; o.y = acc[i][1];
            *reinterpret_cast<ulonglong2*>(g_Qp + (size_t)gr * 256 + h * 64 + (cg << 2)) = o;
        }
    }
}

// ---------------- fused attention: online segment softmax + weighted sum ----------------
__global__ __launch_bounds__(256) void attn_kernel(const float* __restrict__ x, int n) {
    int r = (blockIdx.x << 3) + (threadIdx.x >> 5);
    if (r >= n) return;
    int lane = threadIdx.x & 31;
    int j = lane & 7;

    const float4* qr = reinterpret_cast<const float4*>(g_Qp + (size_t)r * 256);
    float4 q0 = qr[lane * 2], q1 = qr[lane * 2 + 1];

    int beg = g_rowptr[r], end = g_rowptr[r + 1];
    float m = -1e30f, dsum = 0.f;
    float4 a0 = make_float4(0.f, 0.f, 0.f, 0.f);
    float4 a1 = a0;

    for (int p = beg; p < end; p++) {
        int s = g_esend[p];
        const float4* xs = reinterpret_cast<const float4*>(x + (size_t)s * 64);
        float4 v0 = xs[j * 2], v1 = xs[j * 2 + 1];

        float part = q0.x * v0.x + q0.y * v0.y + q0.z * v0.z + q0.w * v0.w
                   + q1.x * v1.x + q1.y * v1.y + q1.z * v1.z + q1.w * v1.w;
        part += __shfl_xor_sync(0xffffffffu, part, 1);
        part += __shfl_xor_sync(0xffffffffu, part, 2);
        part += __shfl_xor_sync(0xffffffffu, part, 4);

        float mn = fmaxf(m, part);
        float c  = __expf(m - mn);
        float pe = __expf(part - mn);
        dsum = dsum * c + pe;
        a0.x = a0.x * c + pe * v0.x; a0.y = a0.y * c + pe * v0.y;
        a0.z = a0.z * c + pe * v0.z; a0.w = a0.w * c + pe * v0.w;
        a1.x = a1.x * c + pe * v1.x; a1.y = a1.y * c + pe * v1.y;
        a1.z = a1.z * c + pe * v1.z; a1.w = a1.w * c + pe * v1.w;
        m = mn;
    }

    float rinv = (dsum > 0.f) ? (1.0f / dsum) : 0.f;
    a0.x *= rinv; a0.y *= rinv; a0.z *= rinv; a0.w *= rinv;
    a1.x *= rinv; a1.y *= rinv; a1.z *= rinv; a1.w *= rinv;

    float4* tr = reinterpret_cast<float4*>(g_T + (size_t)r * 256);
    tr[lane * 2] = a0;
    tr[lane * 2 + 1] = a1;
}

// ---------------- GEMM 2: out = x + T @ Wst  (N x 256)@(256 x 64), f32x2-packed ----------------
__global__ __launch_bounds__(256) void gemm_out_kernel(const float* __restrict__ x,
                                                       float* __restrict__ out, int n) {
    __shared__ float As[128][64];
    __shared__ float Bs[64][64];
    int row0 = blockIdx.x * 128;
    int tid = threadIdx.x;
    int rg = tid >> 4, cg = tid & 15;

    unsigned long long acc[8][2];
    #pragma unroll
    for (int i = 0; i < 8; i++) { acc[i][0] = 0ull; acc[i][1] = 0ull; }

    for (int kc = 0; kc < 4; kc++) {
        const float4* Bg = reinterpret_cast<const float4*>(g_Wst + kc * 64 * 64);
        for (int i = tid; i < 1024; i += 256)
            reinterpret_cast<float4*>(&Bs[0][0])[i] = Bg[i];
        for (int i = tid; i < 2048; i += 256) {
            int r = i >> 4, k4 = (i & 15) << 2;
            int gr = row0 + r;
            float4 v = make_float4(0.f, 0.f, 0.f, 0.f);
            if (gr < n) v = *reinterpret_cast<const float4*>(g_T + (size_t)gr * 256 + kc * 64 + k4);
            *reinterpret_cast<float4*>(&As[r][k4]) = v;
        }
        __syncthreads();

        #pragma unroll 8
        for (int k = 0; k < 64; k += 2) {
            unsigned long long b00 = *reinterpret_cast<const unsigned long long*>(&Bs[k][cg << 2]);
            unsigned long long b01 = *reinterpret_cast<const unsigned long long*>(&Bs[k][(cg << 2) + 2]);
            unsigned long long b10 = *reinterpret_cast<const unsigned long long*>(&Bs[k + 1][cg << 2]);
            unsigned long long b11 = *reinterpret_cast<const unsigned long long*>(&Bs[k + 1][(cg << 2) + 2]);
            #pragma unroll
            for (int i = 0; i < 8; i++) {
                unsigned long long a2 = *reinterpret_cast<const unsigned long long*>(&As[(rg << 3) + i][k]);
                unsigned int alo, ahi;
                asm("mov.b64 {%0, %1}, %2;" : "=r"(alo), "=r"(ahi) : "l"(a2));
                unsigned long long aa0, aa1;
                DUP2(aa0, alo);
                DUP2(aa1, ahi);
                FMA2(acc[i][0], aa0, b00);
                FMA2(acc[i][1], aa0, b01);
                FMA2(acc[i][0], aa1, b10);
                FMA2(acc[i][1], aa1, b11);
            }
        }
        __syncthreads();
    }

    #pragma unroll
    for (int i = 0; i < 8; i++) {
        int gr = row0 + (rg << 3) + i;
        if (gr < n) {
            ulonglong2 xv = *reinterpret_cast<const ulonglong2*>(x + (size_t)gr * 64 + (cg << 2));
            ulonglong2 o;
            ADD2(o.x, acc[i][0], xv.x);
            ADD2(o.y, acc[i][1], xv.y);
            *reinterpret_cast<ulonglong2*>(out + (size_t)gr * 64 + (cg << 2)) = o;
        }
    }
}

// ---------------- launch ----------------
extern "C" void kernel_launch(void* const* d_in, const int* in_sizes, int n_in,
                              void* d_out, int out_size) {
    const float* x    = (const float*)d_in[0];
    const float* Wq   = (const float*)d_in[1];
    const float* Wk   = (const float*)d_in[2];
    const float* Wv   = (const float*)d_in[3];
    const float* Wout = (const float*)d_in[4];
    const int*   ei   = (const int*)d_in[5];

    int n = in_sizes[0] / FEAT;       // 50000
    int E = in_sizes[5] / 2;          // 400000
    const int* send = ei;
    const int* recv = ei + E;
    int nb = (n + 1023) / 1024;       // 49

    prep_mats_kernel<<<8, 256>>>(Wq, Wk, Wv, Wout);

    // CSR build (parallel scan)
    zero_deg_kernel<<<(n + 511) / 512, 512>>>(n);
    count_deg_kernel<<<(E + 511) / 512, 512>>>(recv, E);
    scan_blocks_kernel<<<nb, 1024>>>(n);
    scan_tops_kernel<<<1, 32>>>(nb, n);
    scan_add_kernel<<<nb, 1024>>>(n);
    scatter_edges_kernel<<<(E + 511) / 512, 512>>>(send, recv, E);

    // Q' projection
    dim3 g1((n + 127) / 128, HEADS);
    gemm_qp_kernel<<<g1, 256>>>(x, n);

    // fused per-receiver attention (online softmax)
    attn_kernel<<<(n + 7) / 8, 256>>>(x, n);

    // output projection + residual
    gemm_out_kernel<<<(n + 127) / 128, 256>>>(x, (float*)d_out, n);
}